// round 9
// baseline (speedup 1.0000x reference)
#include <cuda_runtime.h>
#include <cuda_fp16.h>
#include <cstdint>
#include <cstddef>

// ----------------------------------------------------------------------------
// Problem dims
// ----------------------------------------------------------------------------
static constexpr int BSZ   = 2048;
static constexpr int NCPG  = 20000;
static constexpr int NGENE = 4000;
static constexpr int NPATH = 500;
static constexpr int NGENE_PAD = 4096;
static constexpr int NPATH_PAD = 512;
static constexpr int K1PAD = 20032;          // NCPG padded to 64
static constexpr int K1C   = K1PAD / 2;      // compressed row length (10016 halves)
static constexpr int NBLK  = K1PAD / 32;     // 626 k32-blocks per row
static constexpr int MAXR  = 1 << 20;        // residual capacity

// Scratch (device globals: allocation-free rule)
__device__ __half   g_X  [(size_t)BSZ * K1PAD];          // x fp16, K-padded
__device__ __half   g_W1T[(size_t)NGENE_PAD * K1PAD];    // (W1*mask)^T fp16 (intermediate)
__device__ __half   g_W1S[(size_t)NGENE_PAD * K1C];      // 2:4 compressed W1T
__device__ uint32_t g_W1M[(size_t)NGENE_PAD * NBLK];     // 2:4 metadata (8 nibbles/row/block)
__device__ __half   g_W2T[(size_t)NPATH_PAD * NGENE_PAD];// (W2*mask)^T fp16
__device__ __half   g_H  [(size_t)BSZ * NGENE_PAD];      // layer-1 activations fp16
__device__ float    g_R1 [(size_t)BSZ * NGENE_PAD];      // residual (overflow) accumulator
__device__ uint32_t g_RK [MAXR];                         // residual keys (gene<<16 | k)
__device__ float    g_RV [MAXR];                         // residual values
__device__ int      g_RCNT;                              // residual count

#define DINL __device__ __forceinline__

DINL uint32_t smem_u32(const void* p) {
    uint32_t a;
    asm("{ .reg .u64 t; cvta.to.shared.u64 t, %1; cvt.u32.u64 %0, t; }" : "=r"(a) : "l"(p));
    return a;
}

#define CP_ASYNC16(dst, src) \
    asm volatile("cp.async.cg.shared.global [%0], [%1], 16;" :: "r"(dst), "l"(src))
#define CP_ASYNC8(dst, src) \
    asm volatile("cp.async.ca.shared.global [%0], [%1], 8;" :: "r"(dst), "l"(src))
#define CP_COMMIT() asm volatile("cp.async.commit_group;" ::: "memory")
#define CP_WAIT(n)  asm volatile("cp.async.wait_group %0;" :: "n"(n) : "memory")

#define LDSM_X4(r, addr)                                                        \
    asm volatile("ldmatrix.sync.aligned.m8n8.x4.shared.b16 {%0,%1,%2,%3}, [%4];"\
        : "=r"((r)[0]), "=r"((r)[1]), "=r"((r)[2]), "=r"((r)[3]) : "r"(addr))

DINL void mma_f16(float* d, const uint32_t* a, const uint32_t* b) {
    asm volatile(
        "mma.sync.aligned.m16n8k16.row.col.f32.f16.f16.f32 "
        "{%0,%1,%2,%3}, {%4,%5,%6,%7}, {%8,%9}, {%0,%1,%2,%3};"
        : "+f"(d[0]), "+f"(d[1]), "+f"(d[2]), "+f"(d[3])
        : "r"(a[0]), "r"(a[1]), "r"(a[2]), "r"(a[3]), "r"(b[0]), "r"(b[1]));
}

// Sparse 2:4 MMA, ordered metadata (indices sorted ascending), selector 0.
DINL void mma_sp_f16(float* d, const uint32_t* a, const uint32_t* b, uint32_t e) {
    asm volatile(
        "mma.sp::ordered_metadata.sync.aligned.m16n8k32.row.col.f32.f16.f16.f32 "
        "{%0,%1,%2,%3}, {%4,%5,%6,%7}, {%8,%9,%10,%11}, {%0,%1,%2,%3}, %12, 0x0;"
        : "+f"(d[0]), "+f"(d[1]), "+f"(d[2]), "+f"(d[3])
        : "r"(a[0]), "r"(a[1]), "r"(a[2]), "r"(a[3]),
          "r"(b[0]), "r"(b[1]), "r"(b[2]), "r"(b[3]), "r"(e));
}

// ----------------------------------------------------------------------------
// Premask + transpose to fp16: WT[n][k] = h( W[k][n] * M[k][n] ); zero padding.
// ----------------------------------------------------------------------------
__global__ void premask_transpose_h(const float* __restrict__ W, const float* __restrict__ Mk,
                                    __half* __restrict__ WT, int K, int Kpad, int N) {
    __shared__ float tile[32][33];
    const int k0 = blockIdx.x * 32, n0 = blockIdx.y * 32;
    const int tx = threadIdx.x, ty = threadIdx.y;  // 32 x 8
#pragma unroll
    for (int j = 0; j < 32; j += 8) {
        const int k = k0 + ty + j, n = n0 + tx;
        float v = 0.0f;
        if (k < K && n < N) v = W[(size_t)k * N + n] * Mk[(size_t)k * N + n];
        tile[ty + j][tx] = v;
    }
    __syncthreads();
#pragma unroll
    for (int j = 0; j < 32; j += 8) {
        const int n = n0 + ty + j, k = k0 + tx;
        WT[(size_t)n * Kpad + k] = __float2half_rn(tile[tx][ty + j]);
    }
}

// ----------------------------------------------------------------------------
// x (fp32) -> fp16, K-padded with zeros. Also resets the residual counter.
// ----------------------------------------------------------------------------
__global__ void round_x_h(const float* __restrict__ in, __half* __restrict__ out,
                          int K, int Kpad) {
    if (blockIdx.x == 0 && blockIdx.y == 0 && threadIdx.x == 0) g_RCNT = 0;
    const int c = blockIdx.x * blockDim.x + threadIdx.x;  // 8-elem chunk
    const int row = blockIdx.y;
    if (c >= Kpad / 8) return;
    const int col0 = c * 8;
    __half h[8];
    if (col0 + 8 <= K) {
        const float4 v1 = reinterpret_cast<const float4*>(in + (size_t)row * K + col0)[0];
        const float4 v2 = reinterpret_cast<const float4*>(in + (size_t)row * K + col0)[1];
        h[0] = __float2half_rn(v1.x); h[1] = __float2half_rn(v1.y);
        h[2] = __float2half_rn(v1.z); h[3] = __float2half_rn(v1.w);
        h[4] = __float2half_rn(v2.x); h[5] = __float2half_rn(v2.y);
        h[6] = __float2half_rn(v2.z); h[7] = __float2half_rn(v2.w);
    } else {
#pragma unroll
        for (int e = 0; e < 8; ++e) {
            const int col = col0 + e;
            h[e] = (col < K) ? __float2half_rn(in[(size_t)row * K + col]) : __half(0.0f);
        }
    }
    *reinterpret_cast<uint4*>(out + (size_t)row * Kpad + col0) = *reinterpret_cast<uint4*>(h);
}

// ----------------------------------------------------------------------------
// 2:4 compression of g_W1T. One thread per (gene row, 32-k block).
// Metadata word: nibble per 4-chunk (8 chunks), idx0 (bits 0-1) < idx1 (2-3).
// Overflow (3rd/4th nonzero of a chunk) -> exact residual list.
// ----------------------------------------------------------------------------
__global__ void compress_w1(const __half* __restrict__ WT, __half* __restrict__ WS,
                            uint32_t* __restrict__ META) {
    const int idx = blockIdx.x * blockDim.x + threadIdx.x;
    if (idx >= NGENE_PAD * NBLK) return;
    const int row = idx / NBLK, blk = idx % NBLK;
    const __half* src = WT + (size_t)row * K1PAD + blk * 32;
    __half out[16];
    uint32_t meta = 0;
#pragma unroll
    for (int c = 0; c < 8; ++c) {
        __half v[4];
#pragma unroll
        for (int i = 0; i < 4; ++i) v[i] = src[c * 4 + i];
        int nz[4], nnz = 0;
#pragma unroll
        for (int i = 0; i < 4; ++i)
            if (__half2float(v[i]) != 0.0f) nz[nnz++] = i;
        int s0, s1;
        if (nnz >= 2) {
            s0 = nz[0]; s1 = nz[1];
            for (int j = 2; j < nnz; ++j) {  // exact residual for overflow
                const int slot = atomicAdd(&g_RCNT, 1);
                if (slot < MAXR) {
                    g_RK[slot] = ((uint32_t)row << 16) | (uint32_t)(blk * 32 + c * 4 + nz[j]);
                    g_RV[slot] = __half2float(v[nz[j]]);
                }
            }
        } else if (nnz == 1) {
            s0 = nz[0]; s1 = (nz[0] < 3) ? nz[0] + 1 : nz[0];  // pad with a zero elem
            if (s1 == s0) { s1 = s0; s0 = s0 - 1; }            // keep s0 < s1
        } else {
            s0 = 0; s1 = 1;
        }
        out[c * 2 + 0] = v[s0];
        out[c * 2 + 1] = v[s1];
        meta |= (uint32_t)(s0 | (s1 << 2)) << (4 * c);
    }
    uint4* dst = reinterpret_cast<uint4*>(WS + (size_t)row * K1C + blk * 16);
    dst[0] = *reinterpret_cast<uint4*>(out);
    dst[1] = *reinterpret_cast<uint4*>(out + 8);
    META[(size_t)row * NBLK + blk] = meta;
}

// ----------------------------------------------------------------------------
// Residual pass: one CTA per batch row b. Stages x row in smem, accumulates
// residual (gene,k,w) contributions into a per-gene fp32 array, writes R1[b][*].
// ----------------------------------------------------------------------------
__global__ __launch_bounds__(256)
void residual_bx(const __half* __restrict__ X, float* __restrict__ R1) {
    extern __shared__ char sm[];
    __half* xs = reinterpret_cast<__half*>(sm);                 // 20032 halves
    float* hacc = reinterpret_cast<float*>(sm + K1PAD * 2);     // 4096 floats
    const int b = blockIdx.x, tid = threadIdx.x;
    const uint4* xg = reinterpret_cast<const uint4*>(X + (size_t)b * K1PAD);
    for (int i = tid; i < K1PAD / 8; i += 256) reinterpret_cast<uint4*>(xs)[i] = xg[i];
    for (int i = tid; i < NGENE_PAD; i += 256) hacc[i] = 0.0f;
    __syncthreads();
    const int n = min(g_RCNT, MAXR);
    for (int i = tid; i < n; i += 256) {
        const uint32_t key = g_RK[i];
        atomicAdd(&hacc[key >> 16], g_RV[i] * __half2float(xs[key & 0xFFFF]));
    }
    __syncthreads();
    float* dst = R1 + (size_t)b * NGENE_PAD;
    for (int i = tid; i < NGENE_PAD; i += 256) dst[i] = hacc[i];
}

// ----------------------------------------------------------------------------
// Sparse GEMM1: D[g][b] = sum_k W1S[g][k'] (2:4) * X[b][k], fp32 accum.
// CTA tile 128 genes x 256 batch, BK=64 dense k, 4 stages, 256 threads.
// Metadata per thread (PTX m16n8k32 f16, selector 0):
//   T4i   : rows {i, i+8}, chunks 0-3 (k0-15)  = (w_i & 0xFFFF) | (w_i8 << 16)
//   T4i+1 : rows {i, i+8}, chunks 4-7 (k16-31) = (w_i >> 16) | (w_i8 & 0xFFFF0000)
// ----------------------------------------------------------------------------
__global__ __launch_bounds__(256, 1)
void binn_gemm1_sp(const __half* __restrict__ WS, const uint32_t* __restrict__ META,
                   const __half* __restrict__ X, const float* __restrict__ R1,
                   __half* __restrict__ H,
                   const float* __restrict__ bias, const float* __restrict__ gamma,
                   const float* __restrict__ beta, const float* __restrict__ mean,
                   const float* __restrict__ var) {
    constexpr int S = 4;
    constexpr uint32_t ASTG = 128 * 128;           // A: 128 rows x 128B (64B data)
    constexpr uint32_t BSTG = 256 * 128;           // B: 256 rows x 128B
    constexpr uint32_t MSTG = 128 * 8;             // meta: 128 rows x 2 u32
    constexpr uint32_t STG  = ASTG + BSTG + MSTG;  // 50176
    constexpr int T = K1PAD / 64;                  // 313

    extern __shared__ char dsm[];
    float* s_bias = reinterpret_cast<float*>(dsm + S * STG);
    float* s_inv  = s_bias + 128;
    float* s_sh   = s_inv + 128;

    const int tid = threadIdx.x;
    const int wid = tid >> 5, lane = tid & 31;
    const int wm = wid & 1, wn = wid >> 1;         // gene-half, batch-quarter
    const int g0 = blockIdx.x * 128, b0 = blockIdx.y * 256;
    const uint32_t sbase = smem_u32(dsm);

    if (tid < 128) {
        const int g = g0 + tid;
        const bool val = g < NGENE;
        const float ga = val ? gamma[g] : 1.0f;
        const float vv = val ? var[g]   : 1.0f;
        const float be = val ? beta[g]  : 0.0f;
        const float mu = val ? mean[g]  : 0.0f;
        const float bi = val ? bias[g]  : 0.0f;
        const float inv = ga * rsqrtf(vv + 1e-3f);
        s_inv[tid] = inv; s_sh[tid] = be - mu * inv; s_bias[tid] = bi;
    }

    auto load_stage = [&](int buf, int kt) {
        const uint32_t abase = sbase + buf * STG;
#pragma unroll
        for (int i = 0; i < 2; ++i) {              // A: 512 16B-chunks
            const int idx = i * 256 + tid;
            const int r = idx >> 2, ch = idx & 3;
            const uint32_t dst = abase + r * 128 + ((ch ^ (r & 7)) << 4);
            CP_ASYNC16(dst, WS + (size_t)(g0 + r) * K1C + kt * 32 + ch * 8);
        }
        const uint32_t bbase = abase + ASTG;
#pragma unroll
        for (int i = 0; i < 8; ++i) {              // B: 2048 16B-chunks
            const int idx = i * 256 + tid;
            const int r = idx >> 3, ch = idx & 7;
            const uint32_t dst = bbase + r * 128 + ((ch ^ (r & 7)) << 4);
            CP_ASYNC16(dst, X + (size_t)(b0 + r) * K1PAD + kt * 64 + ch * 8);
        }
        if (tid < 128)                             // metadata: 8B per gene row
            CP_ASYNC8(abase + ASTG + BSTG + tid * 8,
                      META + (size_t)(g0 + tid) * NBLK + kt * 2);
    };

#pragma unroll
    for (int s = 0; s < S - 1; ++s) { load_stage(s, s); CP_COMMIT(); }

    float acc[32 * 4];
#pragma unroll
    for (int i = 0; i < 32 * 4; ++i) acc[i] = 0.0f;

    const uint32_t lsw   = lane & 7;
    const uint32_t aoffL = (uint32_t)(wm * 64 + (lane & 15)) * 128;
    const uint32_t boffL = (uint32_t)(wn * 64 + (lane & 7) + ((lane >> 4) << 3)) * 128;
    const uint32_t cAL   = (uint32_t)(lane >> 4);
    const uint32_t cBL   = (uint32_t)((lane >> 3) & 1);
    const int mrow0 = wm * 64 + (lane >> 2);       // metadata row i (pair is i, i+8)
    const uint32_t ksel = lane & 1;                // 0: chunks 0-3, 1: chunks 4-7

    for (int t = 0; t < T; ++t) {
        CP_WAIT(S - 2);
        __syncthreads();
        if (t + S - 1 < T) load_stage((t + S - 1) % S, t + S - 1);
        CP_COMMIT();

        const uint32_t apS = sbase + (t % S) * STG;
        const uint32_t bpS = apS + ASTG;
        const uint32_t* mS = reinterpret_cast<const uint32_t*>(dsm + (t % S) * STG + ASTG + BSTG);
#pragma unroll
        for (int kk = 0; kk < 2; ++kk) {           // two k32 blocks per BK=64
            uint32_t a[4][4];
            const uint32_t swA = (((uint32_t)(kk * 2) + cAL) ^ lsw) << 4;
#pragma unroll
            for (int mt = 0; mt < 4; ++mt)
                LDSM_X4(a[mt], apS + aoffL + mt * 2048 + swA);
            uint32_t bq[4][2][4];
#pragma unroll
            for (int p = 0; p < 4; ++p)
#pragma unroll
                for (int h = 0; h < 2; ++h) {
                    const uint32_t swB = (((uint32_t)(kk * 4 + h * 2) + cBL) ^ lsw) << 4;
                    LDSM_X4(bq[p][h], bpS + boffL + p * 2048 + swB);
                }
            uint32_t e[4];
#pragma unroll
            for (int mt = 0; mt < 4; ++mt) {
                const uint32_t w_i  = mS[(mrow0 + mt * 16) * 2 + kk];
                const uint32_t w_i8 = mS[(mrow0 + mt * 16 + 8) * 2 + kk];
                const uint32_t e_lo = (w_i & 0x0000FFFFu) | (w_i8 << 16);
                const uint32_t e_hi = (w_i >> 16) | (w_i8 & 0xFFFF0000u);
                e[mt] = ksel ? e_hi : e_lo;
            }
#pragma unroll
            for (int mt = 0; mt < 4; ++mt)
#pragma unroll
                for (int nt = 0; nt < 8; ++nt) {
                    const uint32_t bb[4] = {
                        bq[nt >> 1][0][(nt & 1) * 2], bq[nt >> 1][0][(nt & 1) * 2 + 1],
                        bq[nt >> 1][1][(nt & 1) * 2], bq[nt >> 1][1][(nt & 1) * 2 + 1]};
                    mma_sp_f16(&acc[(mt * 8 + nt) * 4], a[mt], bb, e[mt]);
                }
        }
    }

    // ---------------- Epilogue: transpose-stage, fuse residual+bias+relu+BN ----
    CP_WAIT(0);
    __syncthreads();
    float* stg = reinterpret_cast<float*>(dsm);    // [256 b][stride 133]
#pragma unroll
    for (int mt = 0; mt < 4; ++mt)
#pragma unroll
        for (int nt = 0; nt < 8; ++nt) {
            const float* d = &acc[(mt * 8 + nt) * 4];
            const int gl = wm * 64 + mt * 16 + (lane >> 2);
            const int bl = wn * 64 + nt * 8 + 2 * (lane & 3);
            stg[(bl + 0) * 133 + gl]     = d[0];
            stg[(bl + 1) * 133 + gl]     = d[1];
            stg[(bl + 0) * 133 + gl + 8] = d[2];
            stg[(bl + 1) * 133 + gl + 8] = d[3];
        }
    __syncthreads();
    {
        const int b = tid;                          // one batch row per thread
        const float* r1 = R1 + (size_t)(b0 + b) * NGENE_PAD + g0;
        __half* hout = H + (size_t)(b0 + b) * NGENE_PAD + g0;
        const float* row = stg + b * 133;
#pragma unroll 4
        for (int g = 0; g < 128; g += 2) {
            float v0 = row[g]     + r1[g]     + s_bias[g];
            float v1 = row[g + 1] + r1[g + 1] + s_bias[g + 1];
            v0 = fmaxf(v0, 0.0f) * s_inv[g]     + s_sh[g];
            v1 = fmaxf(v1, 0.0f) * s_inv[g + 1] + s_sh[g + 1];
            *reinterpret_cast<__half2*>(hout + g) = __floats2half2_rn(v0, v1);
        }
    }
}

// ----------------------------------------------------------------------------
// Dense GEMM2 (R7 ldmatrix kernel, BN=128, tanh path)
// ----------------------------------------------------------------------------
template <int BN, int LAYER>
__global__ __launch_bounds__(256, 1)
void binn_gemm(const __half* __restrict__ A, const __half* __restrict__ Bt,
               void* __restrict__ OutV, int Kdim, int Nvalid, int ldo,
               const float* __restrict__ bias, const float* __restrict__ gamma,
               const float* __restrict__ beta, const float* __restrict__ mean,
               const float* __restrict__ var) {
    constexpr int BM = 128, BK = 64, S = 4;
    constexpr int WN = BN / 4;
    constexpr int NT = WN / 8;
    constexpr int NP = NT / 2;
    constexpr int MT = 4;
    constexpr uint32_t ASTG = BM * 128;
    constexpr uint32_t BSTG = BN * 128;
    constexpr uint32_t STG  = ASTG + BSTG;

    extern __shared__ char dsm[];
    float* s_inv  = reinterpret_cast<float*>(dsm + S * STG);
    float* s_sh   = s_inv + BN;
    float* s_bias = s_sh + BN;

    const int tid = threadIdx.x;
    const int wid = tid >> 5, lane = tid & 31;
    const int wm = wid & 1, wn = wid >> 1;
    const int l4 = lane & 3, l2 = lane >> 2;
    const int m0 = blockIdx.y * BM, n0 = blockIdx.x * BN;

    if (tid < BN) {
        const int n = n0 + tid;
        const bool v = n < Nvalid;
        const float g  = v ? gamma[n] : 1.0f;
        const float vv = v ? var[n]   : 1.0f;
        const float be = v ? beta[n]  : 0.0f;
        const float mu = v ? mean[n]  : 0.0f;
        const float bi = v ? bias[n]  : 0.0f;
        const float inv = g * rsqrtf(vv + 1e-3f);
        s_inv[tid] = inv; s_sh[tid] = be - mu * inv; s_bias[tid] = bi;
    }

    const __half* Ab = A + (size_t)m0 * Kdim;
    const __half* Bb = Bt + (size_t)n0 * Kdim;
    const uint32_t sbase = smem_u32(dsm);

    auto load_stage = [&](int buf, int kt) {
        const uint32_t abase = sbase + buf * STG;
        const __half* ag = Ab + kt * BK;
#pragma unroll
        for (int i = 0; i < BM * 8 / 256; ++i) {
            const int idx = i * 256 + tid;
            const int r = idx >> 3, ch = idx & 7;
            const uint32_t dst = abase + r * 128 + ((ch ^ (r & 7)) << 4);
            CP_ASYNC16(dst, ag + (size_t)r * Kdim + ch * 8);
        }
        const uint32_t bbase = abase + ASTG;
        const __half* bg = Bb + kt * BK;
#pragma unroll
        for (int i = 0; i < BN * 8 / 256; ++i) {
            const int idx = i * 256 + tid;
            const int r = idx >> 3, ch = idx & 7;
            const uint32_t dst = bbase + r * 128 + ((ch ^ (r & 7)) << 4);
            CP_ASYNC16(dst, bg + (size_t)r * Kdim + ch * 8);
        }
    };

    const int T = Kdim / BK;
#pragma unroll
    for (int s = 0; s < S - 1; ++s) { load_stage(s, s); CP_COMMIT(); }

    float acc[MT * NT * 4];
#pragma unroll
    for (int i = 0; i < MT * NT * 4; ++i) acc[i] = 0.0f;

    const uint32_t lsw   = lane & 7;
    const uint32_t aoffL = (uint32_t)(wm * 64 + (lane & 15)) * 128;
    const uint32_t boffL = (uint32_t)(wn * WN + (lane & 7) + ((lane >> 4) << 3)) * 128;
    const uint32_t cAL   = (uint32_t)(lane >> 4);
    const uint32_t cBL   = (uint32_t)((lane >> 3) & 1);

    for (int t = 0; t < T; ++t) {
        CP_WAIT(S - 2);
        __syncthreads();
        if (t + S - 1 < T) load_stage((t + S - 1) % S, t + S - 1);
        CP_COMMIT();

        const uint32_t apS = sbase + (t % S) * STG;
        const uint32_t bpS = apS + ASTG;
#pragma unroll
        for (int kk = 0; kk < 4; ++kk) {
            const uint32_t swA = (((uint32_t)(kk * 2) + cAL) ^ lsw) << 4;
            const uint32_t swB = (((uint32_t)(kk * 2) + cBL) ^ lsw) << 4;
            uint32_t a[MT][4], b[NP][4];
#pragma unroll
            for (int mt = 0; mt < MT; ++mt)
                LDSM_X4(a[mt], apS + aoffL + mt * 2048 + swA);
#pragma unroll
            for (int p = 0; p < NP; ++p)
                LDSM_X4(b[p], bpS + boffL + p * 2048 + swB);
#pragma unroll
            for (int mt = 0; mt < MT; ++mt)
#pragma unroll
                for (int nt = 0; nt < NT; ++nt)
                    mma_f16(&acc[(mt * NT + nt) * 4], a[mt], &b[nt >> 1][(nt & 1) * 2]);
        }
    }

#pragma unroll
    for (int mt = 0; mt < MT; ++mt) {
#pragma unroll
        for (int nt = 0; nt < NT; ++nt) {
            const float* d = &acc[(mt * NT + nt) * 4];
            const int ncol = wn * WN + nt * 8 + l4 * 2;
            const int n = n0 + ncol;
#pragma unroll
            for (int half = 0; half < 2; ++half) {
                const int m = m0 + wm * 64 + mt * 16 + l2 + half * 8;
                float v0 = d[half * 2 + 0] + s_bias[ncol];
                float v1 = d[half * 2 + 1] + s_bias[ncol + 1];
                v0 = tanhf(v0 * s_inv[ncol]     + s_sh[ncol]);
                v1 = tanhf(v1 * s_inv[ncol + 1] + s_sh[ncol + 1]);
                if (n < Nvalid) {
                    float2 o; o.x = v0; o.y = v1;
                    *reinterpret_cast<float2*>((float*)OutV + (size_t)m * ldo + n) = o;
                }
            }
        }
    }
}

// ----------------------------------------------------------------------------
// kernel_launch
// ----------------------------------------------------------------------------
extern "C" void kernel_launch(void* const* d_in, const int* in_sizes, int n_in,
                              void* d_out, int out_size) {
    const float* x      = (const float*)d_in[0];
    const float* m1     = (const float*)d_in[1];
    const float* m2     = (const float*)d_in[2];
    const float* W1     = (const float*)d_in[3];
    const float* b1     = (const float*)d_in[4];
    const float* W2     = (const float*)d_in[5];
    const float* b2     = (const float*)d_in[6];
    const float* gamma1 = (const float*)d_in[7];
    const float* beta1  = (const float*)d_in[8];
    const float* mean1  = (const float*)d_in[9];
    const float* var1   = (const float*)d_in[10];
    const float* gamma2 = (const float*)d_in[11];
    const float* beta2  = (const float*)d_in[12];
    const float* mean2  = (const float*)d_in[13];
    const float* var2   = (const float*)d_in[14];

    __half *xh, *w1t, *w1s, *w2t, *h;
    uint32_t* w1m;
    float* r1;
    cudaGetSymbolAddress((void**)&xh,  g_X);
    cudaGetSymbolAddress((void**)&w1t, g_W1T);
    cudaGetSymbolAddress((void**)&w1s, g_W1S);
    cudaGetSymbolAddress((void**)&w1m, g_W1M);
    cudaGetSymbolAddress((void**)&w2t, g_W2T);
    cudaGetSymbolAddress((void**)&h,   g_H);
    cudaGetSymbolAddress((void**)&r1,  g_R1);

    const int smem_sp = 4 * 50176 + 1536;                          // 202240
    const int smem2   = 4 * (128 * 128 + 128 * 128) + 3 * 128 * 4; // 132608
    const int smem_r  = K1PAD * 2 + NGENE_PAD * 4;                 // 56448
    cudaFuncSetAttribute(binn_gemm1_sp,    cudaFuncAttributeMaxDynamicSharedMemorySize, smem_sp);
    cudaFuncSetAttribute(binn_gemm<128,2>, cudaFuncAttributeMaxDynamicSharedMemorySize, smem2);
    cudaFuncSetAttribute(residual_bx,      cudaFuncAttributeMaxDynamicSharedMemorySize, smem_r);

    // 1) x -> fp16 (also resets residual counter)
    round_x_h<<<dim3((K1PAD / 8 + 255) / 256, BSZ), 256>>>(x, xh, NCPG, K1PAD);

    // 2) masked transposed weights; compress W1 to 2:4 + residual list
    const dim3 tb(32, 8);
    premask_transpose_h<<<dim3(K1PAD / 32, NGENE_PAD / 32), tb>>>(W1, m1, w1t, NCPG, K1PAD, NGENE);
    compress_w1<<<(NGENE_PAD * NBLK + 255) / 256, 256>>>(w1t, w1s, w1m);
    premask_transpose_h<<<dim3(NGENE_PAD / 32, NPATH_PAD / 32), tb>>>(W2, m2, w2t, NGENE, NGENE_PAD, NPATH);

    // 3) residual accumulation R1[b][g]
    residual_bx<<<BSZ, 256, smem_r>>>(xh, r1);

    // 4) sparse GEMM1 -> h[b][g]
    binn_gemm1_sp<<<dim3(NGENE_PAD / 128, BSZ / 256), 256, smem_sp>>>(
        w1s, w1m, xh, r1, h, b1, gamma1, beta1, mean1, var1);

    // 5) dense GEMM2 -> out = tanh(BN2(h @ W2m + b2))
    binn_gemm<128, 2><<<dim3(NPATH_PAD / 128, BSZ / 128), 256, smem2>>>(
        h, w2t, d_out, NGENE_PAD, NPATH, NPATH, b2, gamma2, beta2, mean2, var2);
}